// round 2
// baseline (speedup 1.0000x reference)
#include <cuda_runtime.h>
#include <cuda_fp16.h>
#include <cstdint>
#include <cstddef>

#define Bq 64
#define Sq 1024
#define Dq 512
#define Hq 1024
#define NBLK 128
#define BSH ((size_t)Bq * Sq * Hq)

// ---------------- persistent device state (no runtime allocation) ----------------
__device__ __half g_x16[(size_t)Bq * Sq * Dq];       // x converted to fp16, [B][S][D]
__device__ __half g_pack0[(size_t)4096 * 1536];      // layer0 fragment-packed weights
__device__ __half g_pack1[(size_t)4096 * 2048];      // layer1 fragment-packed weights
__device__ __half g_h0[2][Bq * Hq];                  // h0 state, batch-major [b][h], parity buffered
__device__ __half g_h1[2][Bq * Hq];                  // h1 state
__device__ float  g_c0[Bq * Hq];                     // c0 state, [h][b]
__device__ float  g_c1[Bq * Hq];                     // c1 state, [h][b]
__device__ unsigned g_bar_count;
__device__ volatile unsigned g_bar_gen;

// ---------------- prep kernels ----------------
__global__ void convert_x_kernel(const float* __restrict__ x) {
    const int n2 = (Bq * Sq * Dq) / 2;
    __half2* dst = reinterpret_cast<__half2*>(g_x16);
    const float2* src = reinterpret_cast<const float2*>(x);
    for (int i = blockIdx.x * blockDim.x + threadIdx.x; i < n2;
         i += gridDim.x * blockDim.x) {
        float2 v = src[i];
        dst[i] = __floats2half2_rn(v.x, v.y);
    }
}

// Pack [W_ih | W_hh] into mma-fragment-major fp16:
// half index = (((t_id*NK + s)*32 + lane)*8 + q2*2 + {0,1})
// t_id = cta*2 + rh ; tile rows r_cta = rh*16 + r_local ; gate q = r_cta/8 ;
// W row = q*1024 + cta*8 + (r_cta%8) ; k = s*16 + frag-k(lane,q2)
__global__ void pack_kernel(const float* __restrict__ Wa, const float* __restrict__ Wb,
                            int Ka, int Kb, int NK, int layer) {
    int total = 256 * NK * 128;  // half2 units = G*K/2
    int u = blockIdx.x * blockDim.x + threadIdx.x;
    if (u >= total) return;
    int q2   = u & 3;
    int lane = (u >> 2) & 31;
    int rest = u >> 7;
    int s    = rest % NK;
    int t_id = rest / NK;
    int rl = (lane >> 2) + ((q2 & 1) << 3);
    int kl = ((lane & 3) << 1) + ((q2 & 2) << 2);
    int c = t_id >> 1, rh = t_id & 1;
    int r_cta = rh * 16 + rl;
    int row = (r_cta >> 3) * 1024 + c * 8 + (r_cta & 7);
    int kg = s * 16 + kl;
    float v0, v1;
    if (kg < Ka) {
        v0 = Wa[(size_t)row * Ka + kg];
        v1 = Wa[(size_t)row * Ka + kg + 1];
    } else {
        int kk = kg - Ka;
        v0 = Wb[(size_t)row * Kb + kk];
        v1 = Wb[(size_t)row * Kb + kk + 1];
    }
    __half2* dst = reinterpret_cast<__half2*>(layer ? g_pack1 : g_pack0);
    dst[u] = __floats2half2_rn(v0, v1);
}

__global__ void init_kernel() {
    int tid = blockIdx.x * blockDim.x + threadIdx.x;
    const int n = Bq * Hq;
    for (int i = tid; i < n; i += gridDim.x * blockDim.x) {
        __half z = __float2half(0.0f);
        g_h0[0][i] = z; g_h0[1][i] = z;
        g_h1[0][i] = z; g_h1[1][i] = z;
        g_c0[i] = 0.0f; g_c1[i] = 0.0f;
    }
    if (tid == 0) { g_bar_count = 0; g_bar_gen = 0; }
}

// ---------------- main persistent kernel ----------------
// smem layout (dynamic, 108800 B total):
//   As  : uint4[2][1024]           (A frags, 2 bufs x 16KB)          @ 0
//   Zs  : half[2][64*264]          (z batch-major, padded rows)      @ 32768
//   gbuf: float[32][66]            (gate exchange)                   @ 100352
#define SMEM_BYTES 108800

__device__ __forceinline__ void grid_sync() {
    __threadfence();
    __syncthreads();
    if (threadIdx.x == 0) {
        unsigned gen = g_bar_gen;
        if (atomicAdd(&g_bar_count, 1) == NBLK - 1) {
            g_bar_count = 0;
            __threadfence();
            g_bar_gen = gen + 1;
        } else {
            while (g_bar_gen == gen) { }
        }
    }
    __syncthreads();
}

#define MMA16816(d, a, b0, b1)                                            \
    asm volatile("mma.sync.aligned.m16n8k16.row.col.f32.f16.f16.f32 "      \
                 "{%0,%1,%2,%3}, {%4,%5,%6,%7}, {%8,%9}, {%0,%1,%2,%3};\n" \
                 : "+f"(d[0]), "+f"(d[1]), "+f"(d[2]), "+f"(d[3])          \
                 : "r"(a.x), "r"(a.y), "r"(a.z), "r"(a.w), "r"(b0), "r"(b1))

__device__ __forceinline__ void cpa16(void* dst, const void* src) {
    unsigned d = (unsigned)__cvta_generic_to_shared(dst);
    asm volatile("cp.async.cg.shared.global [%0], [%1], 16;\n" :: "r"(d), "l"(src));
}

__device__ __forceinline__ void do_layer(int l, int t,
                                         const float* __restrict__ bi,
                                         const float* __restrict__ bh,
                                         float* __restrict__ out) {
    extern __shared__ char smem_[];
    uint4*  As   = reinterpret_cast<uint4*>(smem_);
    __half* Zs   = reinterpret_cast<__half*>(smem_ + 32768);
    float*  gbuf = reinterpret_cast<float*>(smem_ + 100352);

    const int tid  = threadIdx.x;
    const int NCH  = l ? 8 : 6;
    const int NK   = l ? 128 : 96;
    const __half* pb = l ? g_pack1 : g_pack0;

    float a0[4] = {0.f, 0.f, 0.f, 0.f};
    float a1[4] = {0.f, 0.f, 0.f, 0.f};

    auto load_chunk = [&](int ch, int buf) {
        // A fragments: 1024 x 16B, contiguous per rh
        #pragma unroll
        for (int i = 0; i < 4; i++) {
            int o = tid + i * 256;
            int rh = o >> 9, rest = o & 511;
            const __half* src =
                pb + ((size_t)(blockIdx.x * 2 + rh) * NK + ch * 16) * 256 + rest * 8;
            cpa16(As + buf * 1024 + o, src);
        }
        // z chunk: 64 rows x 256 halves (padded to 264 in smem)
        const __half* base; size_t rstride; size_t off;
        if (l == 0) {
            if (ch < 2) { base = g_x16; rstride = (size_t)Sq * Dq; off = (size_t)t * Dq + ch * 256; }
            else        { base = g_h0[(t + 1) & 1]; rstride = Hq; off = (size_t)(ch * 256 - 512); }
        } else {
            if (ch < 4) { base = g_h0[t & 1]; rstride = Hq; off = (size_t)(ch * 256); }
            else        { base = g_h1[(t + 1) & 1]; rstride = Hq; off = (size_t)(ch * 256 - 1024); }
        }
        #pragma unroll
        for (int i = 0; i < 8; i++) {
            int o = tid + i * 256;
            int b = o >> 5, seg = o & 31;
            const __half* src = base + (size_t)b * rstride + off + seg * 8;
            cpa16(Zs + buf * 16896 + b * 264 + seg * 8, src);
        }
        asm volatile("cp.async.commit_group;\n" ::);
    };

    const int lane = tid & 31, w = tid >> 5;
    const int rh = w & 1, cg = w >> 1;

    load_chunk(0, 0);
    for (int ch = 0; ch < NCH; ++ch) {
        if (ch + 1 < NCH) {
            load_chunk(ch + 1, (ch + 1) & 1);
            asm volatile("cp.async.wait_group 1;\n" ::);
        } else {
            asm volatile("cp.async.wait_group 0;\n" ::);
        }
        __syncthreads();
        {
            const int buf = ch & 1;
            const uint4*  Ab = As + buf * 1024 + rh * 512 + lane;
            const __half* zb = Zs + buf * 16896 + (cg * 16 + (lane >> 2)) * 264 + ((lane & 3) << 1);
            #pragma unroll
            for (int sl = 0; sl < 16; ++sl) {
                uint4 a = Ab[sl * 32];
                unsigned b00 = *reinterpret_cast<const unsigned*>(zb + sl * 16);
                unsigned b01 = *reinterpret_cast<const unsigned*>(zb + sl * 16 + 8);
                unsigned b10 = *reinterpret_cast<const unsigned*>(zb + 2112 + sl * 16);
                unsigned b11 = *reinterpret_cast<const unsigned*>(zb + 2112 + sl * 16 + 8);
                MMA16816(a0, a, b00, b01);
                MMA16816(a1, a, b10, b11);
            }
        }
        __syncthreads();
    }

    // epilogue: exchange gates through smem, then fused LSTM cell
    {
        int r0  = rh * 16 + (lane >> 2);
        int col = cg * 16 + ((lane & 3) << 1);
        gbuf[r0 * 66 + col]           = a0[0];
        gbuf[r0 * 66 + col + 1]       = a0[1];
        gbuf[(r0 + 8) * 66 + col]     = a0[2];
        gbuf[(r0 + 8) * 66 + col + 1] = a0[3];
        gbuf[r0 * 66 + col + 8]       = a1[0];
        gbuf[r0 * 66 + col + 9]       = a1[1];
        gbuf[(r0 + 8) * 66 + col + 8] = a1[2];
        gbuf[(r0 + 8) * 66 + col + 9] = a1[3];
    }
    __syncthreads();

    float*  cst  = l ? g_c1 : g_c0;
    __half* hdst = l ? g_h1[t & 1] : g_h0[t & 1];
    #pragma unroll
    for (int it = 0; it < 2; ++it) {
        int p  = tid + it * 256;
        int hr = p >> 6, b = p & 63;
        int hh = blockIdx.x * 8 + hr;
        float gi = gbuf[hr * 66 + b]        + bi[hh]        + bh[hh];
        float gf = gbuf[(8 + hr) * 66 + b]  + bi[1024 + hh] + bh[1024 + hh];
        float gg = gbuf[(16 + hr) * 66 + b] + bi[2048 + hh] + bh[2048 + hh];
        float go = gbuf[(24 + hr) * 66 + b] + bi[3072 + hh] + bh[3072 + hh];
        float iv = 1.0f / (1.0f + __expf(-gi));
        float fv = 1.0f / (1.0f + __expf(-gf));
        float gv = tanhf(gg);
        float ov = 1.0f / (1.0f + __expf(-go));
        float cprev = cst[hh * 64 + b];
        float cn = fv * cprev + iv * gv;
        float hn = ov * tanhf(cn);
        cst[hh * 64 + b] = cn;
        hdst[(size_t)b * Hq + hh] = __float2half_rn(hn);
        if (l) {
            size_t ob = (size_t)b * Sq * Hq + (size_t)t * Hq + hh;
            out[ob] = hn;
            out[BSH + ob] = cn;
            if (t == Sq - 1) {
                out[2 * BSH + (size_t)b * Hq + hh] = hn;
                out[2 * BSH + (size_t)Bq * Hq + (size_t)b * Hq + hh] = cn;
            }
        }
    }
    __syncthreads();
}

__global__ void __launch_bounds__(256, 1)
lstm_main(const float* __restrict__ bi0, const float* __restrict__ bh0,
          const float* __restrict__ bi1, const float* __restrict__ bh1,
          float* __restrict__ out) {
    // phase p: layer0 computes step p, layer1 computes step p-1 (pipelined),
    // one grid barrier per phase.
    for (int p = 0; p <= Sq; ++p) {
        if (p < Sq)  do_layer(0, p,     bi0, bh0, out);
        if (p >= 1)  do_layer(1, p - 1, bi1, bh1, out);
        grid_sync();
    }
}

// ---------------- launch ----------------
extern "C" void kernel_launch(void* const* d_in, const int* in_sizes, int n_in,
                              void* d_out, int out_size) {
    (void)in_sizes; (void)n_in; (void)out_size;
    const float* x    = (const float*)d_in[0];
    const float* Wih0 = (const float*)d_in[1];
    const float* Whh0 = (const float*)d_in[2];
    const float* bih0 = (const float*)d_in[3];
    const float* bhh0 = (const float*)d_in[4];
    const float* Wih1 = (const float*)d_in[5];
    const float* Whh1 = (const float*)d_in[6];
    const float* bih1 = (const float*)d_in[7];
    const float* bhh1 = (const float*)d_in[8];
    float* out = (float*)d_out;

    convert_x_kernel<<<8192, 256>>>(x);
    pack_kernel<<<(256 * 96 * 128) / 256, 256>>>(Wih0, Whh0, 512, 1024, 96, 0);
    pack_kernel<<<(256 * 128 * 128) / 256, 256>>>(Wih1, Whh1, 1024, 1024, 128, 1);
    init_kernel<<<256, 256>>>();

    cudaFuncSetAttribute(lstm_main, cudaFuncAttributeMaxDynamicSharedMemorySize, SMEM_BYTES);
    lstm_main<<<NBLK, 256, SMEM_BYTES>>>(bih0, bhh0, bih1, bhh1, out);
}